// round 2
// baseline (speedup 1.0000x reference)
#include <cuda_runtime.h>
#include <cuda_bf16.h>

// Problem: B=16, C=64, H=128, W=128
//   masked_l1[b,c] = sum_hw |pre-gt| * mask
//   nonzero[b,c]   = count(mask != 0)
//   loss = sum_bc( masked_l1 / max(nonzero,1) ) / B
//
// R2 strategy: fix single-wave load imbalance (1024 CTAs / 148 SMs = 6.92,
// 7-vs-6 integer imbalance ~14% = the DRAM% gap). Split each (b,c) row into
// SEGS=4 segments -> 4096 CTAs (27.7/SM, 3.6% imbalance). Segment partials
// are combined per-bc via atomicAdd into __device__ scratch; a tiny finalize
// kernel does the division + final sum.

#define BATCH   16
#define CHAN    64
#define HW      (128 * 128)            // 16384 elems per (b,c)
#define NBC     (BATCH * CHAN)         // 1024
#define SEGS    4
#define SEG_V4  (HW / 4 / SEGS)        // 1024 float4 per segment
#define THREADS 256
#define V4_PER_THREAD (SEG_V4 / THREADS)  // 4

__device__ float g_s[NBC];
__device__ float g_cnt[NBC];

__global__ void zero_scratch_kernel() {
    const int i = blockIdx.x * blockDim.x + threadIdx.x;
    if (i < NBC) { g_s[i] = 0.0f; g_cnt[i] = 0.0f; }
}

__global__ __launch_bounds__(THREADS, 8)
void l1loss_partial_kernel(const float4* __restrict__ pre,
                           const float4* __restrict__ gt,
                           const float4* __restrict__ mask) {
    const int seg  = blockIdx.x;            // 0..4095
    const int bc   = seg >> 2;              // 0..1023
    const int part = seg & (SEGS - 1);      // 0..3
    const long base = (long)bc * (HW / 4) + (long)part * SEG_V4;

    float s   = 0.0f;
    float cnt = 0.0f;

    #pragma unroll
    for (int i = 0; i < V4_PER_THREAD; i++) {
        const long idx = base + threadIdx.x + (long)i * THREADS;
        const float4 p = __ldcs(&pre[idx]);
        const float4 g = __ldcs(&gt[idx]);
        const float4 m = __ldcs(&mask[idx]);
        s += fabsf(p.x - g.x) * m.x;
        s += fabsf(p.y - g.y) * m.y;
        s += fabsf(p.z - g.z) * m.z;
        s += fabsf(p.w - g.w) * m.w;
        cnt += (m.x != 0.0f) ? 1.0f : 0.0f;
        cnt += (m.y != 0.0f) ? 1.0f : 0.0f;
        cnt += (m.z != 0.0f) ? 1.0f : 0.0f;
        cnt += (m.w != 0.0f) ? 1.0f : 0.0f;
    }

    // Warp reduce
    #pragma unroll
    for (int off = 16; off > 0; off >>= 1) {
        s   += __shfl_down_sync(0xFFFFFFFFu, s,   off);
        cnt += __shfl_down_sync(0xFFFFFFFFu, cnt, off);
    }

    __shared__ float sh_s[THREADS / 32];
    __shared__ float sh_c[THREADS / 32];
    const int lane = threadIdx.x & 31;
    const int wid  = threadIdx.x >> 5;
    if (lane == 0) { sh_s[wid] = s; sh_c[wid] = cnt; }
    __syncthreads();

    if (wid == 0) {
        s   = (lane < THREADS / 32) ? sh_s[lane] : 0.0f;
        cnt = (lane < THREADS / 32) ? sh_c[lane] : 0.0f;
        #pragma unroll
        for (int off = 4; off > 0; off >>= 1) {
            s   += __shfl_down_sync(0xFFFFFFFFu, s,   off);
            cnt += __shfl_down_sync(0xFFFFFFFFu, cnt, off);
        }
        if (lane == 0) {
            atomicAdd(&g_s[bc],   s);    // 4096 atomics, 1024 distinct addrs
            atomicAdd(&g_cnt[bc], cnt);
        }
    }
}

__global__ __launch_bounds__(256, 1)
void finalize_kernel(float* __restrict__ out) {
    float q = 0.0f;
    #pragma unroll
    for (int i = threadIdx.x; i < NBC; i += 256) {
        q += g_s[i] / fmaxf(g_cnt[i], 1.0f);
    }
    #pragma unroll
    for (int off = 16; off > 0; off >>= 1)
        q += __shfl_down_sync(0xFFFFFFFFu, q, off);

    __shared__ float sh[8];
    const int lane = threadIdx.x & 31;
    const int wid  = threadIdx.x >> 5;
    if (lane == 0) sh[wid] = q;
    __syncthreads();
    if (wid == 0) {
        q = (lane < 8) ? sh[lane] : 0.0f;
        #pragma unroll
        for (int off = 4; off > 0; off >>= 1)
            q += __shfl_down_sync(0xFFFFFFFFu, q, off);
        if (lane == 0) out[0] = q * (1.0f / (float)BATCH);
    }
}

extern "C" void kernel_launch(void* const* d_in, const int* in_sizes, int n_in,
                              void* d_out, int out_size) {
    const float4* pre  = (const float4*)d_in[0];
    const float4* gt   = (const float4*)d_in[1];
    const float4* mask = (const float4*)d_in[2];
    float* out = (float*)d_out;

    zero_scratch_kernel<<<(NBC + 255) / 256, 256>>>();
    l1loss_partial_kernel<<<NBC * SEGS, THREADS>>>(pre, gt, mask);
    finalize_kernel<<<1, 256>>>(out);
}

// round 3
// speedup vs baseline: 1.1159x; 1.1159x over previous
#include <cuda_runtime.h>
#include <cuda_bf16.h>

// Problem: B=16, C=64, H=128, W=128
//   masked_l1[b,c] = sum_hw |pre-gt| * mask
//   nonzero[b,c]   = count(mask != 0)
//   loss = sum_bc( masked_l1 / max(nonzero,1) ) / B
//
// R3: single kernel. 4096 CTAs (4 segments per (b,c) row -> 27.7 CTAs/SM,
// 3.7% integer imbalance vs 14% at 1024 CTAs). Per-bc partials accumulate
// via atomicAdd into __device__ scratch; the LAST finishing CTA (global
// ticket counter) finalizes in-kernel and resets scratch for the next
// graph replay. No auxiliary launches (R2 showed tiny kernels cost ~6.5us
// of graph time).

#define BATCH   16
#define CHAN    64
#define HW      (128 * 128)            // 16384 elems per (b,c)
#define NBC     (BATCH * CHAN)         // 1024
#define SEGS    4
#define NSEG    (NBC * SEGS)           // 4096 CTAs
#define SEG_V4  (HW / 4 / SEGS)        // 1024 float4 per segment
#define THREADS 256
#define V4_PER_THREAD (SEG_V4 / THREADS)  // 4

__device__ float    g_s[NBC];
__device__ float    g_cnt[NBC];
__device__ unsigned g_ctr;

__global__ __launch_bounds__(THREADS, 8)
void l1loss_kernel(const float4* __restrict__ pre,
                   const float4* __restrict__ gt,
                   const float4* __restrict__ mask,
                   float* __restrict__ out) {
    const int seg  = blockIdx.x;            // 0..4095
    const int bc   = seg >> 2;              // 0..1023
    const int part = seg & (SEGS - 1);      // 0..3
    const long base = (long)bc * (HW / 4) + (long)part * SEG_V4;

    float s   = 0.0f;
    float cnt = 0.0f;

    #pragma unroll
    for (int i = 0; i < V4_PER_THREAD; i++) {
        const long idx = base + threadIdx.x + (long)i * THREADS;
        const float4 p = __ldcs(&pre[idx]);
        const float4 g = __ldcs(&gt[idx]);
        const float4 m = __ldcs(&mask[idx]);
        s += fabsf(p.x - g.x) * m.x;
        s += fabsf(p.y - g.y) * m.y;
        s += fabsf(p.z - g.z) * m.z;
        s += fabsf(p.w - g.w) * m.w;
        cnt += (m.x != 0.0f) ? 1.0f : 0.0f;
        cnt += (m.y != 0.0f) ? 1.0f : 0.0f;
        cnt += (m.z != 0.0f) ? 1.0f : 0.0f;
        cnt += (m.w != 0.0f) ? 1.0f : 0.0f;
    }

    // Warp reduce
    #pragma unroll
    for (int off = 16; off > 0; off >>= 1) {
        s   += __shfl_down_sync(0xFFFFFFFFu, s,   off);
        cnt += __shfl_down_sync(0xFFFFFFFFu, cnt, off);
    }

    __shared__ float sh_s[THREADS / 32];
    __shared__ float sh_c[THREADS / 32];
    __shared__ int   sh_last;
    const int lane = threadIdx.x & 31;
    const int wid  = threadIdx.x >> 5;
    if (lane == 0) { sh_s[wid] = s; sh_c[wid] = cnt; }
    __syncthreads();

    if (threadIdx.x < 32) {
        s   = (lane < THREADS / 32) ? sh_s[lane] : 0.0f;
        cnt = (lane < THREADS / 32) ? sh_c[lane] : 0.0f;
        #pragma unroll
        for (int off = 4; off > 0; off >>= 1) {
            s   += __shfl_down_sync(0xFFFFFFFFu, s,   off);
            cnt += __shfl_down_sync(0xFFFFFFFFu, cnt, off);
        }
        if (lane == 0) {
            atomicAdd(&g_s[bc],   s);
            atomicAdd(&g_cnt[bc], cnt);
            __threadfence();
            const unsigned old = atomicAdd(&g_ctr, 1u);
            sh_last = (old == (unsigned)(NSEG - 1)) ? 1 : 0;
        }
    }
    __syncthreads();

    // Last CTA finalizes: divide per-bc, sum, write scalar, reset scratch.
    if (sh_last) {
        float q = 0.0f;
        #pragma unroll
        for (int i = threadIdx.x; i < NBC; i += THREADS) {
            const float ss = __ldcg(&g_s[i]);     // bypass L1 (written via L2 atomics)
            const float cc = __ldcg(&g_cnt[i]);
            q += ss / fmaxf(cc, 1.0f);
            g_s[i]   = 0.0f;                      // reset for next replay
            g_cnt[i] = 0.0f;
        }
        #pragma unroll
        for (int off = 16; off > 0; off >>= 1)
            q += __shfl_down_sync(0xFFFFFFFFu, q, off);

        if (lane == 0) sh_s[wid] = q;
        __syncthreads();
        if (threadIdx.x < 32) {
            q = (lane < THREADS / 32) ? sh_s[lane] : 0.0f;
            #pragma unroll
            for (int off = 4; off > 0; off >>= 1)
                q += __shfl_down_sync(0xFFFFFFFFu, q, off);
            if (lane == 0) {
                out[0] = q * (1.0f / (float)BATCH);
                g_ctr  = 0;                       // reset ticket for next replay
            }
        }
    }
}

extern "C" void kernel_launch(void* const* d_in, const int* in_sizes, int n_in,
                              void* d_out, int out_size) {
    const float4* pre  = (const float4*)d_in[0];
    const float4* gt   = (const float4*)d_in[1];
    const float4* mask = (const float4*)d_in[2];
    float* out = (float*)d_out;

    l1loss_kernel<<<NSEG, THREADS>>>(pre, gt, mask, out);
}